// round 13
// baseline (speedup 1.0000x reference)
#include <cuda_runtime.h>
#include <cuda_bf16.h>
#include <cstdint>

#define HID    768
#define NROWS  512          // B*S = 4*128
#define CHUNKS 12           // per part: K = 12*64 = 768
#define STAGES 3
#define STG_SZ 24576        // A 8KB + W 16KB per stage
#define SMEM_TOTAL (STAGES * STG_SZ)

#define BC_M     16                       // m-rows per bulk chunk
#define BC_CHUNK (BC_M * HID * 4)         // 48 KB
#define BC_SMEM  (2 * BC_CHUNK)           // 96 KB double buffer

// ---------------------------------------------------------------------------
// Scratch (__device__ globals; no allocation allowed)
// ---------------------------------------------------------------------------
__device__ __nv_bfloat16 g_A2[2][NROWS][1536];   // [0..767]=ah, [768..]=al
__device__ __nv_bfloat16 g_W2[2][HID][1536];     // [0..767]=wh, [768..]=wl
__device__ float g_part[6][NROWS * HID];         // z*3+part partial products
__device__ float g_proj[2][NROWS * HID];         // reduced (+bias on z==0)

// ---------------------------------------------------------------------------
#define SWZ128(o) ((o) ^ (((o) >> 3) & 0x70))

__device__ __forceinline__ uint32_t smem_u32(const void* p) {
    uint32_t a;
    asm("{ .reg .u64 t; cvta.to.shared.u64 t, %1; cvt.u32.u64 %0, t; }" : "=r"(a) : "l"(p));
    return a;
}
__device__ __forceinline__ void split_bf16(float v, __nv_bfloat16& hi, __nv_bfloat16& lo) {
    hi = __float2bfloat16_rn(v);
    lo = __float2bfloat16_rn(v - __bfloat162float(hi));
}

// ===========================================================================
// 1) fused prep, 2 float4s per thread for MLP:
//    blocks [0,384)   rotary+split of review/reply -> g_A2
//    blocks [384,960) split of W -> g_W2
// ===========================================================================
__global__ void prep_kernel(const float* __restrict__ rev,
                            const float* __restrict__ rep,
                            const float* __restrict__ W) {
    const float cexp = -2.0f * 9.210340371976184f / 768.0f;   // -2*ln(1e4)/768
    if (blockIdx.x < 384) {
        int idx = blockIdx.x * 256 + threadIdx.x;     // 0 .. 98303
        int which = idx / (NROWS * 96);
        int rem   = idx - which * (NROWS * 96);
        int row   = rem / 96;
        int q0    = rem - row * 96;                   // 0..95
        int s     = row & 127;

        const float4* in = (const float4*)(which ? rep : rev);
        float4 x0 = in[row * 192 + q0];
        float4 x1 = in[row * 192 + q0 + 96];

        float fs = (float)s;
        float a0 = fs * __expf((float)(2 * q0) * cexp);
        float a1 = fs * __expf((float)(2 * q0 + 1) * cexp);
        float a2 = fs * __expf((float)(2 * (q0 + 96)) * cexp);
        float a3 = fs * __expf((float)(2 * (q0 + 96) + 1) * cexp);
        float c0, s0, c1, s1, c2, s2, c3, s3;
        __sincosf(a0, &s0, &c0);
        __sincosf(a1, &s1, &c1);
        __sincosf(a2, &s2, &c2);
        __sincosf(a3, &s3, &c3);

        float4 o0, o1;
        o0.x = x0.x * c0 - x0.y * s0;
        o0.y = x0.y * c0 + x0.x * s0;
        o0.z = x0.z * c1 - x0.w * s1;
        o0.w = x0.w * c1 + x0.z * s1;
        o1.x = x1.x * c2 - x1.y * s2;
        o1.y = x1.y * c2 + x1.x * s2;
        o1.z = x1.z * c3 - x1.w * s3;
        o1.w = x1.w * c3 + x1.z * s3;

        __nv_bfloat16 h0[4], l0[4], h1[4], l1[4];
        split_bf16(o0.x, h0[0], l0[0]); split_bf16(o0.y, h0[1], l0[1]);
        split_bf16(o0.z, h0[2], l0[2]); split_bf16(o0.w, h0[3], l0[3]);
        split_bf16(o1.x, h1[0], l1[0]); split_bf16(o1.y, h1[1], l1[1]);
        split_bf16(o1.z, h1[2], l1[2]); split_bf16(o1.w, h1[3], l1[3]);

        __nv_bfloat16* dst = &g_A2[which][row][0];
        *(uint2*)&dst[4 * q0]              = *(uint2*)h0;
        *(uint2*)&dst[768 + 4 * q0]        = *(uint2*)l0;
        *(uint2*)&dst[4 * (q0 + 96)]       = *(uint2*)h1;
        *(uint2*)&dst[768 + 4 * (q0 + 96)] = *(uint2*)l1;
    } else {
        int idx = (blockIdx.x - 384) * 256 + threadIdx.x;   // 0 .. 147455
        int z   = idx / (HID * 96);
        int rem = idx - z * (HID * 96);
        int o   = rem / 96;
        int q0  = rem - o * 96;

        float4 w0 = *(const float4*)&W[o * 1536 + z * 768 + 4 * q0];
        float4 w1 = *(const float4*)&W[o * 1536 + z * 768 + 4 * (q0 + 96)];
        __nv_bfloat16 h0[4], l0[4], h1[4], l1[4];
        split_bf16(w0.x, h0[0], l0[0]); split_bf16(w0.y, h0[1], l0[1]);
        split_bf16(w0.z, h0[2], l0[2]); split_bf16(w0.w, h0[3], l0[3]);
        split_bf16(w1.x, h1[0], l1[0]); split_bf16(w1.y, h1[1], l1[1]);
        split_bf16(w1.z, h1[2], l1[2]); split_bf16(w1.w, h1[3], l1[3]);

        __nv_bfloat16* dst = &g_W2[z][o][0];
        *(uint2*)&dst[4 * q0]              = *(uint2*)h0;
        *(uint2*)&dst[768 + 4 * q0]        = *(uint2*)l0;
        *(uint2*)&dst[4 * (q0 + 96)]       = *(uint2*)h1;
        *(uint2*)&dst[768 + 4 * (q0 + 96)] = *(uint2*)l1;
    }
}

// ===========================================================================
// 2) mma.sync bf16 GEMM: one split-2 part per CTA-z slice (K=768 each).
//    Block 64(m) x 128(n), 8 warps (2x4), warp tile 32x32.
//    grid 6(n) x 8(m) x 6(z*3+part) = 288 CTAs -> 2/SM balanced wave.
// ===========================================================================
__global__ __launch_bounds__(256, 2) void gemm_mma_kernel() {
    extern __shared__ __align__(1024) char smem[];
    uint32_t sb = smem_u32(smem);

    int t = threadIdx.x, lane = t & 31, wid = t >> 5;
    int wm = wid >> 2, wn = wid & 3;                  // warp grid 2 x 4
    int zp = blockIdx.z;                              // 0..5
    int z = zp / 3;
    int part = zp - z * 3;
    int rowBase = blockIdx.y * 64;
    int oBase   = blockIdx.x * 128;
    const __nv_bfloat16* A2 = &g_A2[z][0][0];
    const __nv_bfloat16* W2 = &g_W2[z][0][0];
    int aoffBase = (part == 2) ? 768 : 0;             // al for part 2
    int woffBase = (part == 1) ? 768 : 0;             // wl for part 1

    float acc[2][4][4];
    #pragma unroll
    for (int i = 0; i < 2; i++)
        #pragma unroll
        for (int j = 0; j < 4; j++)
            #pragma unroll
            for (int r = 0; r < 4; r++) acc[i][j][r] = 0.0f;

    auto load_chunk = [&](int c) {
        int s = c % STAGES;
        int aoff = aoffBase + c * 64;
        int woff = woffBase + c * 64;
        uint32_t stA = sb + s * STG_SZ;
        uint32_t stW = stA + 8192;
        #pragma unroll
        for (int rep = 0; rep < 6; rep++) {
            int i = t + rep * 256;
            uint32_t dst;
            const void* src;
            if (i < 512) {                            // A: 64 rows x 8 segs
                int r = i >> 3, sg = i & 7;
                dst = stA + SWZ128(r * 128 + sg * 16);
                src = &A2[(rowBase + r) * 1536 + aoff + sg * 8];
            } else {                                  // W: 128 rows x 8 segs
                int j2 = i - 512;
                int r = j2 >> 3, sg = j2 & 7;
                dst = stW + SWZ128(r * 128 + sg * 16);
                src = &W2[(oBase + r) * 1536 + woff + sg * 8];
            }
            asm volatile("cp.async.cg.shared.global [%0], [%1], 16;" :: "r"(dst), "l"(src));
        }
        asm volatile("cp.async.commit_group;" ::: "memory");
    };

    load_chunk(0);
    load_chunk(1);

    for (int c = 0; c < CHUNKS; c++) {
        if (c == CHUNKS - 1) asm volatile("cp.async.wait_group 0;" ::: "memory");
        else                 asm volatile("cp.async.wait_group 1;" ::: "memory");
        __syncthreads();
        if (c + 2 < CHUNKS) load_chunk(c + 2);

        int s = c % STAGES;
        uint32_t stA = sb + s * STG_SZ;
        uint32_t stW = stA + 8192;

        #pragma unroll
        for (int kk = 0; kk < 4; kk++) {              // 4 x k16 per 64-chunk
            uint32_t a[2][4];
            #pragma unroll
            for (int i = 0; i < 2; i++) {
                uint32_t addr = stA + SWZ128((wm * 32 + i * 16 + (lane & 15)) * 128
                                             + kk * 32 + ((lane >> 4) << 4));
                asm volatile("ldmatrix.sync.aligned.m8n8.x4.shared.b16 {%0,%1,%2,%3}, [%4];"
                             : "=r"(a[i][0]), "=r"(a[i][1]), "=r"(a[i][2]), "=r"(a[i][3])
                             : "r"(addr));
            }
            uint32_t b[4][2];
            #pragma unroll
            for (int jp = 0; jp < 2; jp++) {
                int grp = lane >> 3, jl = grp >> 1, h = grp & 1;
                uint32_t addr = stW + SWZ128((wn * 32 + jp * 16 + jl * 8 + (lane & 7)) * 128
                                             + kk * 32 + h * 16);
                uint32_t r0, r1, r2, r3;
                asm volatile("ldmatrix.sync.aligned.m8n8.x4.shared.b16 {%0,%1,%2,%3}, [%4];"
                             : "=r"(r0), "=r"(r1), "=r"(r2), "=r"(r3) : "r"(addr));
                b[jp * 2 + 0][0] = r0; b[jp * 2 + 0][1] = r1;
                b[jp * 2 + 1][0] = r2; b[jp * 2 + 1][1] = r3;
            }
            #pragma unroll
            for (int i = 0; i < 2; i++)
                #pragma unroll
                for (int j = 0; j < 4; j++)
                    asm volatile(
                        "mma.sync.aligned.m16n8k16.row.col.f32.bf16.bf16.f32 "
                        "{%0,%1,%2,%3}, {%4,%5,%6,%7}, {%8,%9}, {%0,%1,%2,%3};"
                        : "+f"(acc[i][j][0]), "+f"(acc[i][j][1]),
                          "+f"(acc[i][j][2]), "+f"(acc[i][j][3])
                        : "r"(a[i][0]), "r"(a[i][1]), "r"(a[i][2]), "r"(a[i][3]),
                          "r"(b[j][0]), "r"(b[j][1]));
        }
    }

    // ---- epilogue: fp32 accum -> g_part[zp] ----
    int lr = lane >> 2, lc = (lane & 3) * 2;
    float* C = g_part[zp];
    #pragma unroll
    for (int i = 0; i < 2; i++) {
        int row = rowBase + wm * 32 + i * 16 + lr;
        #pragma unroll
        for (int j = 0; j < 4; j++) {
            int col = oBase + wn * 32 + j * 8 + lc;
            *(float2*)&C[row * HID + col] =
                make_float2(acc[i][j][0], acc[i][j][1]);
            *(float2*)&C[(row + 8) * HID + col] =
                make_float2(acc[i][j][2], acc[i][j][3]);
        }
    }
}

// ===========================================================================
// 2b) reduce: g_proj[z] = part0 + part1 + part2 (+ bias on z==0)
// ===========================================================================
__global__ __launch_bounds__(256) void reduce_kernel(const float* __restrict__ bias) {
    int z = blockIdx.y;
    int f0 = blockIdx.x * 512 + threadIdx.x;          // float4 idx; +256 pair
    const float4* P0 = (const float4*)g_part[z * 3 + 0];
    const float4* P1 = (const float4*)g_part[z * 3 + 1];
    const float4* P2 = (const float4*)g_part[z * 3 + 2];
    float4* D = (float4*)g_proj[z];
    #pragma unroll
    for (int u = 0; u < 2; u++) {
        int f = f0 + u * 256;
        float4 a = P0[f], b = P1[f], c = P2[f];
        float4 v;
        v.x = a.x + b.x + c.x;
        v.y = a.y + b.y + c.y;
        v.z = a.z + b.z + c.z;
        v.w = a.w + b.w + c.w;
        if (z == 0) {
            float4 bv = ((const float4*)bias)[f % 192];
            v.x += bv.x; v.y += bv.y; v.z += bv.z; v.w += bv.w;
        }
        D[f] = v;
    }
}

// ===========================================================================
// 3) Broadcast add + ReLU via bulk-copy stores:
//    out[b,n,m,:] = relu(pr[b,n,:] + pp[b,m,:])
//    STG.128 issue cost (12 cyc) capped the old kernel at ~21 B/cyc/SM.
//    Here: STS into smem (crossbar, 128 B/cyc) then cp.async.bulk drains
//    smem -> gmem with no per-instruction SM cost. Block computes
//    4(n) x 16(m) x 768 and issues 4 x 48KB contiguous bulk copies.
// ===========================================================================
__global__ __launch_bounds__(192) void bcast_relu_kernel(float* __restrict__ out) {
    extern __shared__ __align__(16) char bsm[];
    int t  = threadIdx.x;           // 0..191 : float4 column index
    int b  = blockIdx.z;
    int n0 = blockIdx.y * 4;
    int m0 = blockIdx.x * BC_M;

    const float4* PR = (const float4*)g_proj[0];
    const float4* PP = (const float4*)g_proj[1];

    float4 pv[BC_M];
    #pragma unroll
    for (int j = 0; j < BC_M; j++) pv[j] = PP[(b * 128 + m0 + j) * 192 + t];
    float4 rv[4];
    #pragma unroll
    for (int i = 0; i < 4; i++) rv[i] = PR[(b * 128 + n0 + i) * 192 + t];

    #pragma unroll 1
    for (int i = 0; i < 4; i++) {
        float4* B = (float4*)bsm + (i & 1) * (BC_M * 192);
        if (i >= 2) {
            // buffer (i&1) was bulk-committed in iteration i-2; wait for
            // its smem reads to finish before overwriting.
            if (t == 0)
                asm volatile("cp.async.bulk.wait_group.read 1;" ::: "memory");
        }
        __syncthreads();
        #pragma unroll
        for (int j = 0; j < BC_M; j++) {
            float4 s;
            s.x = fmaxf(rv[i].x + pv[j].x, 0.0f);
            s.y = fmaxf(rv[i].y + pv[j].y, 0.0f);
            s.z = fmaxf(rv[i].z + pv[j].z, 0.0f);
            s.w = fmaxf(rv[i].w + pv[j].w, 0.0f);
            B[j * 192 + t] = s;
        }
        __syncthreads();
        if (t == 0) {
            asm volatile("fence.proxy.async.shared::cta;" ::: "memory");
            const float* dst = out + (((size_t)(b * 128 + n0 + i)) * 128 + m0) * HID;
            asm volatile("cp.async.bulk.global.shared::cta.bulk_group [%0], [%1], %2;"
                         :: "l"(dst), "r"(smem_u32(B)), "r"((uint32_t)BC_CHUNK)
                         : "memory");
            asm volatile("cp.async.bulk.commit_group;" ::: "memory");
        }
    }
    if (t == 0)
        asm volatile("cp.async.bulk.wait_group 0;" ::: "memory");
    __syncthreads();
}

// ===========================================================================
// inputs: review(4,128,768) reply(4,128,768) W(768,1536) b(768); out fp32
// ===========================================================================
extern "C" void kernel_launch(void* const* d_in, const int* in_sizes, int n_in,
                              void* d_out, int out_size) {
    const float* review = (const float*)d_in[0];
    const float* reply  = (const float*)d_in[1];
    const float* W      = (const float*)d_in[2];
    const float* bias   = (const float*)d_in[3];
    float* out = (float*)d_out;

    static bool attr_set = false;
    if (!attr_set) {
        cudaFuncSetAttribute(gemm_mma_kernel,
                             cudaFuncAttributeMaxDynamicSharedMemorySize, SMEM_TOTAL);
        cudaFuncSetAttribute(bcast_relu_kernel,
                             cudaFuncAttributeMaxDynamicSharedMemorySize, BC_SMEM);
        attr_set = true;
    }

    prep_kernel<<<960, 256>>>(review, reply, W);
    gemm_mma_kernel<<<dim3(6, 8, 6), 256, SMEM_TOTAL>>>();
    reduce_kernel<<<dim3(192, 2), 256>>>(bias);
    bcast_relu_kernel<<<dim3(8, 32, 4), 192, BC_SMEM>>>(out);
}

// round 16
// speedup vs baseline: 1.1597x; 1.1597x over previous
#include <cuda_runtime.h>
#include <cuda_bf16.h>
#include <cstdint>

#define HID    768
#define NROWS  512          // B*S = 4*128
#define CHUNKS 12           // per part: K = 12*64 = 768
#define STAGES 3
#define STG_SZ 24576        // A 8KB + W 16KB per stage
#define SMEM_TOTAL (STAGES * STG_SZ)

// ---------------------------------------------------------------------------
// Scratch (__device__ globals; no allocation allowed)
// ---------------------------------------------------------------------------
__device__ __nv_bfloat16 g_A2[2][NROWS][1536];   // [0..767]=ah, [768..]=al
__device__ __nv_bfloat16 g_W2[2][HID][1536];     // [0..767]=wh, [768..]=wl
__device__ float g_part[6][NROWS * HID];         // z*3+part partial products
__device__ float g_proj[2][NROWS * HID];         // reduced (+bias on z==0)

// ---------------------------------------------------------------------------
#define SWZ128(o) ((o) ^ (((o) >> 3) & 0x70))

__device__ __forceinline__ uint32_t smem_u32(const void* p) {
    uint32_t a;
    asm("{ .reg .u64 t; cvta.to.shared.u64 t, %1; cvt.u32.u64 %0, t; }" : "=r"(a) : "l"(p));
    return a;
}
__device__ __forceinline__ void split_bf16(float v, __nv_bfloat16& hi, __nv_bfloat16& lo) {
    hi = __float2bfloat16_rn(v);
    lo = __float2bfloat16_rn(v - __bfloat162float(hi));
}

// ===========================================================================
// 1) fused prep. Each thread owns TWO ADJACENT float4s (q = 2u, 2u+1) so the
//    8 hi-bf16 and 8 lo-bf16 results are each one contiguous 16B STG.128
//    (prep was STG.64-issue-bound at 4 stores/thread).
//    blocks [0,384)   : rotary+split of review/reply -> g_A2
//    blocks [384,960) : split of W -> g_W2
// ===========================================================================
__global__ void prep_kernel(const float* __restrict__ rev,
                            const float* __restrict__ rep,
                            const float* __restrict__ W) {
    const float cexp = -2.0f * 9.210340371976184f / 768.0f;   // -2*ln(1e4)/768
    if (blockIdx.x < 384) {
        int idx = blockIdx.x * 256 + threadIdx.x;     // 0 .. 98303
        int which = idx / (NROWS * 96);
        int rem   = idx - which * (NROWS * 96);
        int row   = rem / 96;
        int u     = rem - row * 96;                   // 0..95 : float4 pair
        int s     = row & 127;

        const float4* in = (const float4*)(which ? rep : rev);
        float4 x0 = in[row * 192 + 2 * u];            // k = 8u .. 8u+3
        float4 x1 = in[row * 192 + 2 * u + 1];        // k = 8u+4 .. 8u+7

        float fs = (float)s;
        int i0 = 4 * u;                               // rotary pair index base
        float a0 = fs * __expf((float)(i0 + 0) * cexp);
        float a1 = fs * __expf((float)(i0 + 1) * cexp);
        float a2 = fs * __expf((float)(i0 + 2) * cexp);
        float a3 = fs * __expf((float)(i0 + 3) * cexp);
        float c0, s0, c1, s1, c2, s2, c3, s3;
        __sincosf(a0, &s0, &c0);
        __sincosf(a1, &s1, &c1);
        __sincosf(a2, &s2, &c2);
        __sincosf(a3, &s3, &c3);

        float4 o0, o1;
        o0.x = x0.x * c0 - x0.y * s0;
        o0.y = x0.y * c0 + x0.x * s0;
        o0.z = x0.z * c1 - x0.w * s1;
        o0.w = x0.w * c1 + x0.z * s1;
        o1.x = x1.x * c2 - x1.y * s2;
        o1.y = x1.y * c2 + x1.x * s2;
        o1.z = x1.z * c3 - x1.w * s3;
        o1.w = x1.w * c3 + x1.z * s3;

        __nv_bfloat16 h[8], l[8];
        split_bf16(o0.x, h[0], l[0]); split_bf16(o0.y, h[1], l[1]);
        split_bf16(o0.z, h[2], l[2]); split_bf16(o0.w, h[3], l[3]);
        split_bf16(o1.x, h[4], l[4]); split_bf16(o1.y, h[5], l[5]);
        split_bf16(o1.z, h[6], l[6]); split_bf16(o1.w, h[7], l[7]);

        __nv_bfloat16* dst = &g_A2[which][row][0];
        *(uint4*)&dst[8 * u]       = *(uint4*)h;      // one STG.128
        *(uint4*)&dst[768 + 8 * u] = *(uint4*)l;      // one STG.128
    } else {
        int idx = (blockIdx.x - 384) * 256 + threadIdx.x;   // 0 .. 147455
        int z   = idx / (HID * 96);
        int rem = idx - z * (HID * 96);
        int o   = rem / 96;
        int u   = rem - o * 96;

        float4 w0 = *(const float4*)&W[o * 1536 + z * 768 + 8 * u];
        float4 w1 = *(const float4*)&W[o * 1536 + z * 768 + 8 * u + 4];
        __nv_bfloat16 h[8], l[8];
        split_bf16(w0.x, h[0], l[0]); split_bf16(w0.y, h[1], l[1]);
        split_bf16(w0.z, h[2], l[2]); split_bf16(w0.w, h[3], l[3]);
        split_bf16(w1.x, h[4], l[4]); split_bf16(w1.y, h[5], l[5]);
        split_bf16(w1.z, h[6], l[6]); split_bf16(w1.w, h[7], l[7]);

        __nv_bfloat16* dst = &g_W2[z][o][0];
        *(uint4*)&dst[8 * u]       = *(uint4*)h;
        *(uint4*)&dst[768 + 8 * u] = *(uint4*)l;
    }
}

// ===========================================================================
// 2) mma.sync bf16 GEMM: one split-2 part per CTA-z slice (K=768 each).
//    Block 64(m) x 128(n), 8 warps (2x4), warp tile 32x32.
//    grid 6(n) x 8(m) x 6(z*3+part) = 288 CTAs -> 2/SM balanced wave.
//    part 0: ah*wh   part 1: ah*wl   part 2: al*wh
// ===========================================================================
__global__ __launch_bounds__(256, 2) void gemm_mma_kernel() {
    extern __shared__ __align__(1024) char smem[];
    uint32_t sb = smem_u32(smem);

    int t = threadIdx.x, lane = t & 31, wid = t >> 5;
    int wm = wid >> 2, wn = wid & 3;                  // warp grid 2 x 4
    int zp = blockIdx.z;                              // 0..5
    int z = zp / 3;
    int part = zp - z * 3;
    int rowBase = blockIdx.y * 64;
    int oBase   = blockIdx.x * 128;
    const __nv_bfloat16* A2 = &g_A2[z][0][0];
    const __nv_bfloat16* W2 = &g_W2[z][0][0];
    int aoffBase = (part == 2) ? 768 : 0;             // al for part 2
    int woffBase = (part == 1) ? 768 : 0;             // wl for part 1

    float acc[2][4][4];
    #pragma unroll
    for (int i = 0; i < 2; i++)
        #pragma unroll
        for (int j = 0; j < 4; j++)
            #pragma unroll
            for (int r = 0; r < 4; r++) acc[i][j][r] = 0.0f;

    auto load_chunk = [&](int c) {
        int s = c % STAGES;
        int aoff = aoffBase + c * 64;
        int woff = woffBase + c * 64;
        uint32_t stA = sb + s * STG_SZ;
        uint32_t stW = stA + 8192;
        #pragma unroll
        for (int rep = 0; rep < 6; rep++) {
            int i = t + rep * 256;
            uint32_t dst;
            const void* src;
            if (i < 512) {                            // A: 64 rows x 8 segs
                int r = i >> 3, sg = i & 7;
                dst = stA + SWZ128(r * 128 + sg * 16);
                src = &A2[(rowBase + r) * 1536 + aoff + sg * 8];
            } else {                                  // W: 128 rows x 8 segs
                int j2 = i - 512;
                int r = j2 >> 3, sg = j2 & 7;
                dst = stW + SWZ128(r * 128 + sg * 16);
                src = &W2[(oBase + r) * 1536 + woff + sg * 8];
            }
            asm volatile("cp.async.cg.shared.global [%0], [%1], 16;" :: "r"(dst), "l"(src));
        }
        asm volatile("cp.async.commit_group;" ::: "memory");
    };

    load_chunk(0);
    load_chunk(1);

    for (int c = 0; c < CHUNKS; c++) {
        if (c == CHUNKS - 1) asm volatile("cp.async.wait_group 0;" ::: "memory");
        else                 asm volatile("cp.async.wait_group 1;" ::: "memory");
        __syncthreads();
        if (c + 2 < CHUNKS) load_chunk(c + 2);

        int s = c % STAGES;
        uint32_t stA = sb + s * STG_SZ;
        uint32_t stW = stA + 8192;

        #pragma unroll
        for (int kk = 0; kk < 4; kk++) {              // 4 x k16 per 64-chunk
            uint32_t a[2][4];
            #pragma unroll
            for (int i = 0; i < 2; i++) {
                uint32_t addr = stA + SWZ128((wm * 32 + i * 16 + (lane & 15)) * 128
                                             + kk * 32 + ((lane >> 4) << 4));
                asm volatile("ldmatrix.sync.aligned.m8n8.x4.shared.b16 {%0,%1,%2,%3}, [%4];"
                             : "=r"(a[i][0]), "=r"(a[i][1]), "=r"(a[i][2]), "=r"(a[i][3])
                             : "r"(addr));
            }
            uint32_t b[4][2];
            #pragma unroll
            for (int jp = 0; jp < 2; jp++) {
                int grp = lane >> 3, jl = grp >> 1, h = grp & 1;
                uint32_t addr = stW + SWZ128((wn * 32 + jp * 16 + jl * 8 + (lane & 7)) * 128
                                             + kk * 32 + h * 16);
                uint32_t r0, r1, r2, r3;
                asm volatile("ldmatrix.sync.aligned.m8n8.x4.shared.b16 {%0,%1,%2,%3}, [%4];"
                             : "=r"(r0), "=r"(r1), "=r"(r2), "=r"(r3) : "r"(addr));
                b[jp * 2 + 0][0] = r0; b[jp * 2 + 0][1] = r1;
                b[jp * 2 + 1][0] = r2; b[jp * 2 + 1][1] = r3;
            }
            #pragma unroll
            for (int i = 0; i < 2; i++)
                #pragma unroll
                for (int j = 0; j < 4; j++)
                    asm volatile(
                        "mma.sync.aligned.m16n8k16.row.col.f32.bf16.bf16.f32 "
                        "{%0,%1,%2,%3}, {%4,%5,%6,%7}, {%8,%9}, {%0,%1,%2,%3};"
                        : "+f"(acc[i][j][0]), "+f"(acc[i][j][1]),
                          "+f"(acc[i][j][2]), "+f"(acc[i][j][3])
                        : "r"(a[i][0]), "r"(a[i][1]), "r"(a[i][2]), "r"(a[i][3]),
                          "r"(b[j][0]), "r"(b[j][1]));
        }
    }

    // ---- epilogue: fp32 accum -> g_part[zp] ----
    int lr = lane >> 2, lc = (lane & 3) * 2;
    float* C = g_part[zp];
    #pragma unroll
    for (int i = 0; i < 2; i++) {
        int row = rowBase + wm * 32 + i * 16 + lr;
        #pragma unroll
        for (int j = 0; j < 4; j++) {
            int col = oBase + wn * 32 + j * 8 + lc;
            *(float2*)&C[row * HID + col] =
                make_float2(acc[i][j][0], acc[i][j][1]);
            *(float2*)&C[(row + 8) * HID + col] =
                make_float2(acc[i][j][2], acc[i][j][3]);
        }
    }
}

// ===========================================================================
// 2b) reduce: g_proj[z] = part0 + part1 + part2 (+ bias on z==0)
//     2 float4s per thread for MLP; L2-resident.
// ===========================================================================
__global__ __launch_bounds__(256) void reduce_kernel(const float* __restrict__ bias) {
    int z = blockIdx.y;
    int f0 = blockIdx.x * 512 + threadIdx.x;          // float4 idx; +256 pair
    const float4* P0 = (const float4*)g_part[z * 3 + 0];
    const float4* P1 = (const float4*)g_part[z * 3 + 1];
    const float4* P2 = (const float4*)g_part[z * 3 + 2];
    float4* D = (float4*)g_proj[z];
    #pragma unroll
    for (int u = 0; u < 2; u++) {
        int f = f0 + u * 256;
        float4 a = P0[f], b = P1[f], c = P2[f];
        float4 v;
        v.x = a.x + b.x + c.x;
        v.y = a.y + b.y + c.y;
        v.z = a.z + b.z + c.z;
        v.w = a.w + b.w + c.w;
        if (z == 0) {
            float4 bv = ((const float4*)bias)[f % 192];
            v.x += bv.x; v.y += bv.y; v.z += bv.z; v.w += bv.w;
        }
        D[f] = v;
    }
}

// ===========================================================================
// 3) Broadcast add + ReLU: out[b,n,m,:] = relu(pr[b,n,:] + pp[b,m,:])
//    4x4 (n x m) tile. STG.128 issue-rate floor: ~21.3 B/cyc/SM -> ~33us.
// ===========================================================================
__global__ __launch_bounds__(192) void bcast_relu_kernel(float* __restrict__ out) {
    int t  = threadIdx.x;           // 0..191 : float4 column index
    int b  = blockIdx.z;
    int n0 = blockIdx.y * 4;
    int m0 = blockIdx.x * 4;

    const float4* PR = (const float4*)g_proj[0];
    const float4* PP = (const float4*)g_proj[1];

    float4 rv[4], pv[4];
    #pragma unroll
    for (int i = 0; i < 4; i++) rv[i] = PR[(b * 128 + n0 + i) * 192 + t];
    #pragma unroll
    for (int j = 0; j < 4; j++) pv[j] = PP[(b * 128 + m0 + j) * 192 + t];

    float4* O = (float4*)out;
    int base = ((b * 128 + n0) * 128 + m0) * 192 + t;

    #pragma unroll
    for (int i = 0; i < 4; i++) {
        #pragma unroll
        for (int j = 0; j < 4; j++) {
            float4 s;
            s.x = fmaxf(rv[i].x + pv[j].x, 0.0f);
            s.y = fmaxf(rv[i].y + pv[j].y, 0.0f);
            s.z = fmaxf(rv[i].z + pv[j].z, 0.0f);
            s.w = fmaxf(rv[i].w + pv[j].w, 0.0f);
            __stcs(&O[base + i * (128 * 192) + j * 192], s);
        }
    }
}

// ===========================================================================
// inputs: review(4,128,768) reply(4,128,768) W(768,1536) b(768); out fp32
// ===========================================================================
extern "C" void kernel_launch(void* const* d_in, const int* in_sizes, int n_in,
                              void* d_out, int out_size) {
    const float* review = (const float*)d_in[0];
    const float* reply  = (const float*)d_in[1];
    const float* W      = (const float*)d_in[2];
    const float* bias   = (const float*)d_in[3];
    float* out = (float*)d_out;

    static bool attr_set = false;
    if (!attr_set) {
        cudaFuncSetAttribute(gemm_mma_kernel,
                             cudaFuncAttributeMaxDynamicSharedMemorySize, SMEM_TOTAL);
        attr_set = true;
    }

    prep_kernel<<<960, 256>>>(review, reply, W);
    gemm_mma_kernel<<<dim3(6, 8, 6), 256, SMEM_TOTAL>>>();
    reduce_kernel<<<dim3(192, 2), 256>>>(bias);
    bcast_relu_kernel<<<dim3(32, 32, 4), 192>>>(out);
}